// round 1
// baseline (speedup 1.0000x reference)
#include <cuda_runtime.h>
#include <math.h>

// Problem constants
#define BB   4096
#define NN   64
#define DD   256
#define OUTD 512
#define NIT  3

// ---------------------------------------------------------------------------
// Kernel 1: soft clustering. One block per batch element, 256 threads.
// h[b] (64x256 fp32 = 64KB) staged in dynamic SMEM. Thread t owns mu[t].
// ---------------------------------------------------------------------------
__global__ void __launch_bounds__(256, 3)
cluster_kernel(const float* __restrict__ h,
               const float* __restrict__ log_tau,
               float* __restrict__ out_alpha,   // [B, 64]
               float* __restrict__ out_mu)      // [B, 256]
{
    extern __shared__ float hs[];          // [64 * 256]
    __shared__ float rni[NN];              // 1 / max(||h_row||, eps)
    __shared__ float simv[NN];
    __shared__ float alpha_s[NN];
    __shared__ float mun[DD];
    __shared__ float red[8];

    const int b = blockIdx.x;
    const int t = threadIdx.x;             // 0..255
    const int w = t >> 5;
    const int l = t & 31;

    // --- stage h[b] into smem (coalesced float4) ---
    {
        const float4* src = (const float4*)(h + (size_t)b * NN * DD);
        float4* dst = (float4*)hs;
        #pragma unroll
        for (int i = 0; i < 16; i++)
            dst[t + 256 * i] = src[t + 256 * i];
    }
    __syncthreads();

    float tau = expf(log_tau[0]);
    tau = fminf(fmaxf(tau, 0.01f), 2.0f);
    const float inv_tau = 1.0f / tau;

    // --- initial mu: mean over n (thread t owns dim t) ---
    float m = 0.0f;
    #pragma unroll 8
    for (int n = 0; n < NN; n++)
        m += hs[n * DD + t];
    m *= (1.0f / NN);

    // --- per-row inverse norms (warp w handles rows 8w..8w+7) ---
    #pragma unroll
    for (int i = 0; i < 8; i++) {
        const int n = w * 8 + i;
        float s = 0.0f;
        #pragma unroll
        for (int j = 0; j < 8; j++) {
            float v = hs[n * DD + l + 32 * j];
            s += v * v;
        }
        #pragma unroll
        for (int o = 16; o > 0; o >>= 1) s += __shfl_xor_sync(0xFFFFFFFFu, s, o);
        if (l == 0) rni[n] = 1.0f / fmaxf(sqrtf(s), 1e-12f);
    }
    __syncthreads();

    // --- 3 EM iterations ---
    for (int it = 0; it < NIT; it++) {
        // ||mu||
        float s = m * m;
        #pragma unroll
        for (int o = 16; o > 0; o >>= 1) s += __shfl_xor_sync(0xFFFFFFFFu, s, o);
        if (l == 0) red[w] = s;
        __syncthreads();
        float tot = 0.0f;
        #pragma unroll
        for (int i = 0; i < 8; i++) tot += red[i];
        const float muinv = 1.0f / fmaxf(sqrtf(tot), 1e-12f);
        mun[t] = m * muinv;
        __syncthreads();

        // sim[n] = (h[n] . mu_n) * rni[n] / tau
        #pragma unroll
        for (int i = 0; i < 8; i++) {
            const int n = w * 8 + i;
            float d = 0.0f;
            #pragma unroll
            for (int j = 0; j < 8; j++)
                d += hs[n * DD + l + 32 * j] * mun[l + 32 * j];
            #pragma unroll
            for (int o = 16; o > 0; o >>= 1) d += __shfl_xor_sync(0xFFFFFFFFu, d, o);
            if (l == 0) simv[n] = d * rni[n] * inv_tau;
        }
        __syncthreads();

        // softmax over 64 (warp 0)
        if (w == 0) {
            float a = simv[l];
            float c = simv[l + 32];
            float mx = fmaxf(a, c);
            #pragma unroll
            for (int o = 16; o > 0; o >>= 1)
                mx = fmaxf(mx, __shfl_xor_sync(0xFFFFFFFFu, mx, o));
            float e0 = expf(a - mx);
            float e1 = expf(c - mx);
            float ss = e0 + e1;
            #pragma unroll
            for (int o = 16; o > 0; o >>= 1) ss += __shfl_xor_sync(0xFFFFFFFFu, ss, o);
            float inv = 1.0f / ss;
            alpha_s[l]      = e0 * inv;
            alpha_s[l + 32] = e1 * inv;
        }
        __syncthreads();

        // mu[t] = sum_n alpha[n] * h[n][t]
        float acc = 0.0f;
        #pragma unroll 8
        for (int n = 0; n < NN; n++)
            acc += alpha_s[n] * hs[n * DD + t];
        m = acc;
        __syncthreads();
    }

    // --- write outputs ---
    if (t < NN) out_alpha[(size_t)b * NN + t] = alpha_s[t];
    out_mu[(size_t)b * DD + t] = m;
}

// ---------------------------------------------------------------------------
// Kernel 2: fused MLP: theta = LN2(GELU(LN1(mu @ w1^T + b1)) @ w2^T + b2)
// One block per 16 batch rows, 256 threads. Intermediates live in SMEM.
// Thread microkernel: 4 outputs x 8 rows.
// ---------------------------------------------------------------------------
__global__ void __launch_bounds__(256, 4)
mlp_kernel(const float* __restrict__ mu_in,   // [B, 256]
           const float* __restrict__ w1,      // [512, 256]
           const float* __restrict__ b1,
           const float* __restrict__ g1,
           const float* __restrict__ be1,
           const float* __restrict__ w2,      // [512, 512]
           const float* __restrict__ b2,
           const float* __restrict__ g2,
           const float* __restrict__ be2,
           float* __restrict__ theta)         // [B, 512]
{
    __shared__ float xs[16 * OUTD];           // 32KB; first 16*256 doubles as mu tile

    const int t = threadIdx.x;                 // 0..255
    const int row0 = blockIdx.x * 16;
    const int ox = t & 127;                    // output lane
    const int ry = (t >> 7) * 8;               // row base (0 or 8)
    const int w = t >> 5;
    const int l = t & 31;

    // --- load mu tile [16, 256] into xs ---
    {
        const float4* src = (const float4*)(mu_in + (size_t)row0 * DD);
        float4* dst = (float4*)xs;
        #pragma unroll
        for (int i = 0; i < 4; i++)
            dst[t + 256 * i] = src[t + 256 * i];
    }
    __syncthreads();

    float acc[4][8];
    #pragma unroll
    for (int c = 0; c < 4; c++)
        #pragma unroll
        for (int r = 0; r < 8; r++) acc[c][r] = 0.0f;

    // --- GEMM1: y1 = mu @ w1^T ---
    for (int k = 0; k < DD; k += 4) {
        float4 wv[4];
        #pragma unroll
        for (int c = 0; c < 4; c++)
            wv[c] = *(const float4*)(w1 + (size_t)(ox + 128 * c) * DD + k);
        float4 mv[8];
        #pragma unroll
        for (int r = 0; r < 8; r++)
            mv[r] = *(const float4*)(xs + (ry + r) * DD + k);
        #pragma unroll
        for (int c = 0; c < 4; c++)
            #pragma unroll
            for (int r = 0; r < 8; r++)
                acc[c][r] += wv[c].x * mv[r].x + wv[c].y * mv[r].y
                           + wv[c].z * mv[r].z + wv[c].w * mv[r].w;
    }
    __syncthreads();  // done reading mu tile

    // --- y1 + b1 into xs[16][512] ---
    #pragma unroll
    for (int c = 0; c < 4; c++) {
        const float bb = b1[ox + 128 * c];
        #pragma unroll
        for (int r = 0; r < 8; r++)
            xs[(ry + r) * OUTD + ox + 128 * c] = acc[c][r] + bb;
    }
    __syncthreads();

    // --- LN1 + exact GELU, row-wise (warp w handles rows 2w, 2w+1) ---
    #pragma unroll
    for (int rr = 0; rr < 2; rr++) {
        const int row = w * 2 + rr;
        float s = 0.0f, sq = 0.0f;
        #pragma unroll
        for (int j = 0; j < 16; j++) {
            float v = xs[row * OUTD + l + 32 * j];
            s += v; sq += v * v;
        }
        #pragma unroll
        for (int o = 16; o > 0; o >>= 1) {
            s  += __shfl_xor_sync(0xFFFFFFFFu, s, o);
            sq += __shfl_xor_sync(0xFFFFFFFFu, sq, o);
        }
        const float mean = s * (1.0f / OUTD);
        const float var  = sq * (1.0f / OUTD) - mean * mean;
        const float rstd = rsqrtf(var + 1e-5f);
        #pragma unroll
        for (int j = 0; j < 16; j++) {
            const int idx = l + 32 * j;
            float v = xs[row * OUTD + idx];
            v = (v - mean) * rstd * g1[idx] + be1[idx];
            v = 0.5f * v * (1.0f + erff(v * 0.70710678118654752f));
            xs[row * OUTD + idx] = v;
        }
    }
    __syncthreads();

    // --- GEMM2: y2 = x @ w2^T ---
    #pragma unroll
    for (int c = 0; c < 4; c++)
        #pragma unroll
        for (int r = 0; r < 8; r++) acc[c][r] = 0.0f;

    for (int k = 0; k < OUTD; k += 4) {
        float4 wv[4];
        #pragma unroll
        for (int c = 0; c < 4; c++)
            wv[c] = *(const float4*)(w2 + (size_t)(ox + 128 * c) * OUTD + k);
        float4 mv[8];
        #pragma unroll
        for (int r = 0; r < 8; r++)
            mv[r] = *(const float4*)(xs + (ry + r) * OUTD + k);
        #pragma unroll
        for (int c = 0; c < 4; c++)
            #pragma unroll
            for (int r = 0; r < 8; r++)
                acc[c][r] += wv[c].x * mv[r].x + wv[c].y * mv[r].y
                           + wv[c].z * mv[r].z + wv[c].w * mv[r].w;
    }
    __syncthreads();  // done reading x tile

    // --- y2 + b2 into xs ---
    #pragma unroll
    for (int c = 0; c < 4; c++) {
        const float bb = b2[ox + 128 * c];
        #pragma unroll
        for (int r = 0; r < 8; r++)
            xs[(ry + r) * OUTD + ox + 128 * c] = acc[c][r] + bb;
    }
    __syncthreads();

    // --- LN2 (no activation) ---
    #pragma unroll
    for (int rr = 0; rr < 2; rr++) {
        const int row = w * 2 + rr;
        float s = 0.0f, sq = 0.0f;
        #pragma unroll
        for (int j = 0; j < 16; j++) {
            float v = xs[row * OUTD + l + 32 * j];
            s += v; sq += v * v;
        }
        #pragma unroll
        for (int o = 16; o > 0; o >>= 1) {
            s  += __shfl_xor_sync(0xFFFFFFFFu, s, o);
            sq += __shfl_xor_sync(0xFFFFFFFFu, sq, o);
        }
        const float mean = s * (1.0f / OUTD);
        const float var  = sq * (1.0f / OUTD) - mean * mean;
        const float rstd = rsqrtf(var + 1e-5f);
        #pragma unroll
        for (int j = 0; j < 16; j++) {
            const int idx = l + 32 * j;
            float v = xs[row * OUTD + idx];
            xs[row * OUTD + idx] = (v - mean) * rstd * g2[idx] + be2[idx];
        }
    }
    __syncthreads();

    // --- write theta tile coalesced ---
    {
        float4* dst = (float4*)(theta + (size_t)row0 * OUTD);
        const float4* src = (const float4*)xs;
        #pragma unroll
        for (int i = 0; i < 8; i++)
            dst[t + 256 * i] = src[t + 256 * i];
    }
}

// ---------------------------------------------------------------------------
// Launch. Output layout: [theta (B*512) | alpha (B*64) | mu (B*256)]
// ---------------------------------------------------------------------------
extern "C" void kernel_launch(void* const* d_in, const int* in_sizes, int n_in,
                              void* d_out, int out_size)
{
    const float* h       = (const float*)d_in[0];
    const float* log_tau = (const float*)d_in[1];
    const float* w1      = (const float*)d_in[2];
    const float* b1      = (const float*)d_in[3];
    const float* g1      = (const float*)d_in[4];
    const float* be1     = (const float*)d_in[5];
    const float* w2      = (const float*)d_in[6];
    const float* b2      = (const float*)d_in[7];
    const float* g2      = (const float*)d_in[8];
    const float* be2     = (const float*)d_in[9];

    const int batch = in_sizes[0] / (NN * DD);

    float* out   = (float*)d_out;
    float* theta = out;
    float* alpha = out + (size_t)batch * OUTD;
    float* mu    = out + (size_t)batch * OUTD + (size_t)batch * NN;

    cudaFuncSetAttribute(cluster_kernel,
                         cudaFuncAttributeMaxDynamicSharedMemorySize,
                         NN * DD * (int)sizeof(float));

    cluster_kernel<<<batch, 256, NN * DD * sizeof(float)>>>(h, log_tau, alpha, mu);
    mlp_kernel<<<batch / 16, 256>>>(mu, w1, b1, g1, be1, w2, b2, g2, be2, theta);
}

// round 2
// speedup vs baseline: 2.0117x; 2.0117x over previous
#include <cuda_runtime.h>
#include <math.h>

#define BB   4096
#define NN   64
#define DD   256
#define OUTD 512
#define NIT  3

// Transposed weight scratch (allowed: __device__ globals, not allocation)
__device__ float g_w1t[DD * OUTD];    // [256][512]  w1t[k][o] = w1[o][k]
__device__ float g_w2t[OUTD * OUTD];  // [512][512]  w2t[k][o] = w2[o][k]

// ---------------------------------------------------------------------------
// Tiled transpose: out[c][r] = in[r][c], in is [R][C]
// ---------------------------------------------------------------------------
__global__ void transpose_kernel(const float* __restrict__ in,
                                 float* __restrict__ out, int R, int C)
{
    __shared__ float tile[32][33];
    const int c0 = blockIdx.x * 32;
    const int r0 = blockIdx.y * 32;
    const int tx = threadIdx.x;      // 0..31
    const int ty = threadIdx.y;      // 0..7
    #pragma unroll
    for (int i = 0; i < 4; i++) {
        int r = r0 + ty + 8 * i;
        int c = c0 + tx;
        if (r < R && c < C) tile[ty + 8 * i][tx] = in[(size_t)r * C + c];
    }
    __syncthreads();
    #pragma unroll
    for (int i = 0; i < 4; i++) {
        int c = c0 + ty + 8 * i;
        int r = r0 + tx;
        if (r < R && c < C) out[(size_t)c * R + r] = tile[tx][ty + 8 * i];
    }
}

__device__ __forceinline__ float wsum(float v) {
    #pragma unroll
    for (int o = 16; o > 0; o >>= 1) v += __shfl_xor_sync(0xFFFFFFFFu, v, o);
    return v;
}

// ---------------------------------------------------------------------------
// Kernel 1: soft clustering, register-resident h.
// 256 threads/block. Warp w owns rows [8w,8w+8); lane l owns dims [8l,8l+8).
// ---------------------------------------------------------------------------
__global__ void __launch_bounds__(256, 2)
cluster_kernel(const float* __restrict__ h,
               const float* __restrict__ log_tau,
               float* __restrict__ out_alpha,   // [B, 64]
               float* __restrict__ out_mu)      // [B, 256]
{
    __shared__ float pmu[8][DD];     // per-warp partial mu (8KB)
    __shared__ float simv[NN];
    __shared__ float alpha_s[NN];

    const int b = blockIdx.x;
    const int t = threadIdx.x;
    const int w = t >> 5;
    const int l = t & 31;

    const float* hb = h + (size_t)b * NN * DD;

    // --- load 8 rows x 8 dims into registers (coalesced LDG.128) ---
    float4 hv[8][2];
    #pragma unroll
    for (int r = 0; r < 8; r++) {
        const float* p = hb + (size_t)(8 * w + r) * DD + 8 * l;
        hv[r][0] = *(const float4*)(p);
        hv[r][1] = *(const float4*)(p + 4);
    }

    float tau = expf(log_tau[0]);
    tau = fminf(fmaxf(tau, 0.01f), 2.0f);
    const float inv_tau = 1.0f / tau;

    // --- per-row inverse norms (replicated across lanes) ---
    float rni[8];
    #pragma unroll
    for (int r = 0; r < 8; r++) {
        float4 a = hv[r][0], c = hv[r][1];
        float s = a.x*a.x + a.y*a.y + a.z*a.z + a.w*a.w
                + c.x*c.x + c.y*c.y + c.z*c.z + c.w*c.w;
        s = wsum(s);
        rni[r] = 1.0f / fmaxf(sqrtf(s), 1e-12f);
    }

    // --- initial mu: mean over all 64 rows ---
    float pm[8];
    #pragma unroll
    for (int i = 0; i < 8; i++) pm[i] = 0.0f;
    #pragma unroll
    for (int r = 0; r < 8; r++) {
        pm[0] += hv[r][0].x; pm[1] += hv[r][0].y;
        pm[2] += hv[r][0].z; pm[3] += hv[r][0].w;
        pm[4] += hv[r][1].x; pm[5] += hv[r][1].y;
        pm[6] += hv[r][1].z; pm[7] += hv[r][1].w;
    }
    ((float4*)&pmu[w][8 * l])[0] = make_float4(pm[0], pm[1], pm[2], pm[3]);
    ((float4*)&pmu[w][8 * l])[1] = make_float4(pm[4], pm[5], pm[6], pm[7]);
    __syncthreads();

    float mu[8];
    {
        float acc[8];
        #pragma unroll
        for (int i = 0; i < 8; i++) acc[i] = 0.0f;
        #pragma unroll
        for (int ww = 0; ww < 8; ww++) {
            float4 a = ((float4*)&pmu[ww][8 * l])[0];
            float4 c = ((float4*)&pmu[ww][8 * l])[1];
            acc[0] += a.x; acc[1] += a.y; acc[2] += a.z; acc[3] += a.w;
            acc[4] += c.x; acc[5] += c.y; acc[6] += c.z; acc[7] += c.w;
        }
        #pragma unroll
        for (int i = 0; i < 8; i++) mu[i] = acc[i] * (1.0f / NN);
    }
    __syncthreads();

    // --- 3 EM iterations ---
    for (int it = 0; it < NIT; it++) {
        // normalize mu (each warp computes identically)
        float s = 0.0f;
        #pragma unroll
        for (int i = 0; i < 8; i++) s += mu[i] * mu[i];
        s = wsum(s);
        const float muinv = 1.0f / fmaxf(sqrtf(s), 1e-12f);
        float mun[8];
        #pragma unroll
        for (int i = 0; i < 8; i++) mun[i] = mu[i] * muinv;

        // sim for this warp's 8 rows
        #pragma unroll
        for (int r = 0; r < 8; r++) {
            float4 a = hv[r][0], c = hv[r][1];
            float d = a.x*mun[0] + a.y*mun[1] + a.z*mun[2] + a.w*mun[3]
                    + c.x*mun[4] + c.y*mun[5] + c.z*mun[6] + c.w*mun[7];
            d = wsum(d);
            if (l == 0) simv[8 * w + r] = d * rni[r] * inv_tau;
        }
        __syncthreads();

        // softmax over 64 (warp 0)
        if (w == 0) {
            float a = simv[l];
            float c = simv[l + 32];
            float mx = fmaxf(a, c);
            #pragma unroll
            for (int o = 16; o > 0; o >>= 1)
                mx = fmaxf(mx, __shfl_xor_sync(0xFFFFFFFFu, mx, o));
            float e0 = expf(a - mx);
            float e1 = expf(c - mx);
            float ss = wsum(e0 + e1);
            float inv = 1.0f / ss;
            alpha_s[l]      = e0 * inv;
            alpha_s[l + 32] = e1 * inv;
        }
        __syncthreads();

        // mu update: partial over this warp's rows, then cross-warp reduce
        float al[8];
        #pragma unroll
        for (int r = 0; r < 8; r++) al[r] = alpha_s[8 * w + r];
        #pragma unroll
        for (int i = 0; i < 8; i++) pm[i] = 0.0f;
        #pragma unroll
        for (int r = 0; r < 8; r++) {
            const float a = al[r];
            pm[0] += a * hv[r][0].x; pm[1] += a * hv[r][0].y;
            pm[2] += a * hv[r][0].z; pm[3] += a * hv[r][0].w;
            pm[4] += a * hv[r][1].x; pm[5] += a * hv[r][1].y;
            pm[6] += a * hv[r][1].z; pm[7] += a * hv[r][1].w;
        }
        ((float4*)&pmu[w][8 * l])[0] = make_float4(pm[0], pm[1], pm[2], pm[3]);
        ((float4*)&pmu[w][8 * l])[1] = make_float4(pm[4], pm[5], pm[6], pm[7]);
        __syncthreads();
        {
            float acc[8];
            #pragma unroll
            for (int i = 0; i < 8; i++) acc[i] = 0.0f;
            #pragma unroll
            for (int ww = 0; ww < 8; ww++) {
                float4 a = ((float4*)&pmu[ww][8 * l])[0];
                float4 c = ((float4*)&pmu[ww][8 * l])[1];
                acc[0] += a.x; acc[1] += a.y; acc[2] += a.z; acc[3] += a.w;
                acc[4] += c.x; acc[5] += c.y; acc[6] += c.z; acc[7] += c.w;
            }
            #pragma unroll
            for (int i = 0; i < 8; i++) mu[i] = acc[i];
        }
        __syncthreads();
    }

    // --- outputs ---
    if (t < NN) out_alpha[(size_t)b * NN + t] = alpha_s[t];
    if (w == 0) {
        float* p = out_mu + (size_t)b * DD + 8 * l;
        *(float4*)(p)     = make_float4(mu[0], mu[1], mu[2], mu[3]);
        *(float4*)(p + 4) = make_float4(mu[4], mu[5], mu[6], mu[7]);
    }
}

// ---------------------------------------------------------------------------
// Kernel 2: fused MLP with transposed weights.
// 512 threads, 16 rows/block. Thread tile: 4 consecutive cols x 4 rows.
// ---------------------------------------------------------------------------
__global__ void __launch_bounds__(512, 2)
mlp_kernel(const float* __restrict__ mu_in,   // [B, 256]
           const float* __restrict__ b1,
           const float* __restrict__ g1,
           const float* __restrict__ be1,
           const float* __restrict__ b2,
           const float* __restrict__ g2,
           const float* __restrict__ be2,
           float* __restrict__ theta)         // [B, 512]
{
    __shared__ float xs[16 * OUTD];           // 32KB; first 16*256 holds mu tile

    const int t = threadIdx.x;                 // 0..511
    const int row0 = blockIdx.x * 16;
    const int ox4 = (t & 127) * 4;             // 4 consecutive output cols
    const int ry = (t >> 7) * 4;               // row base {0,4,8,12}
    const int w = t >> 5;                      // 0..15 (one warp per LN row)
    const int l = t & 31;

    // --- load mu tile [16,256] ---
    {
        const float4* src = (const float4*)(mu_in + (size_t)row0 * DD);
        float4* dst = (float4*)xs;
        dst[t]       = src[t];
        dst[t + 512] = src[t + 512];
    }
    __syncthreads();

    float acc[4][4];
    #pragma unroll
    for (int c = 0; c < 4; c++)
        #pragma unroll
        for (int r = 0; r < 4; r++) acc[c][r] = 0.0f;

    // --- GEMM1: y1 = mu @ w1^T  (w1t[k][512]) ---
    for (int k = 0; k < DD; k += 4) {
        float4 wv[4];
        #pragma unroll
        for (int kk = 0; kk < 4; kk++)
            wv[kk] = *(const float4*)(g_w1t + (size_t)(k + kk) * OUTD + ox4);
        #pragma unroll
        for (int r = 0; r < 4; r++) {
            float4 m = *(const float4*)(xs + (ry + r) * DD + k);
            acc[0][r] += wv[0].x*m.x + wv[1].x*m.y + wv[2].x*m.z + wv[3].x*m.w;
            acc[1][r] += wv[0].y*m.x + wv[1].y*m.y + wv[2].y*m.z + wv[3].y*m.w;
            acc[2][r] += wv[0].z*m.x + wv[1].z*m.y + wv[2].z*m.z + wv[3].z*m.w;
            acc[3][r] += wv[0].w*m.x + wv[1].w*m.y + wv[2].w*m.z + wv[3].w*m.w;
        }
    }
    __syncthreads();

    // --- y1 + b1 into xs[16][512] ---
    {
        const float4 bb = *(const float4*)(b1 + ox4);
        #pragma unroll
        for (int r = 0; r < 4; r++) {
            float4 v = make_float4(acc[0][r] + bb.x, acc[1][r] + bb.y,
                                   acc[2][r] + bb.z, acc[3][r] + bb.w);
            *(float4*)(xs + (ry + r) * OUTD + ox4) = v;
        }
    }
    __syncthreads();

    // --- LN1 + exact GELU (warp w handles row w) ---
    {
        float s = 0.0f, sq = 0.0f;
        #pragma unroll
        for (int j = 0; j < 16; j++) {
            float v = xs[w * OUTD + l + 32 * j];
            s += v; sq += v * v;
        }
        #pragma unroll
        for (int o = 16; o > 0; o >>= 1) {
            s  += __shfl_xor_sync(0xFFFFFFFFu, s, o);
            sq += __shfl_xor_sync(0xFFFFFFFFu, sq, o);
        }
        const float mean = s * (1.0f / OUTD);
        const float var  = sq * (1.0f / OUTD) - mean * mean;
        const float rstd = rsqrtf(var + 1e-5f);
        #pragma unroll
        for (int j = 0; j < 16; j++) {
            const int idx = l + 32 * j;
            float v = xs[w * OUTD + idx];
            v = (v - mean) * rstd * g1[idx] + be1[idx];
            v = 0.5f * v * (1.0f + erff(v * 0.70710678118654752f));
            xs[w * OUTD + idx] = v;
        }
    }
    __syncthreads();

    // --- GEMM2: y2 = x @ w2^T  (w2t[k][512]) ---
    #pragma unroll
    for (int c = 0; c < 4; c++)
        #pragma unroll
        for (int r = 0; r < 4; r++) acc[c][r] = 0.0f;

    for (int k = 0; k < OUTD; k += 4) {
        float4 wv[4];
        #pragma unroll
        for (int kk = 0; kk < 4; kk++)
            wv[kk] = *(const float4*)(g_w2t + (size_t)(k + kk) * OUTD + ox4);
        #pragma unroll
        for (int r = 0; r < 4; r++) {
            float4 m = *(const float4*)(xs + (ry + r) * OUTD + k);
            acc[0][r] += wv[0].x*m.x + wv[1].x*m.y + wv[2].x*m.z + wv[3].x*m.w;
            acc[1][r] += wv[0].y*m.x + wv[1].y*m.y + wv[2].y*m.z + wv[3].y*m.w;
            acc[2][r] += wv[0].z*m.x + wv[1].z*m.y + wv[2].z*m.z + wv[3].z*m.w;
            acc[3][r] += wv[0].w*m.x + wv[1].w*m.y + wv[2].w*m.z + wv[3].w*m.w;
        }
    }
    __syncthreads();

    // --- y2 + b2 ---
    {
        const float4 bb = *(const float4*)(b2 + ox4);
        #pragma unroll
        for (int r = 0; r < 4; r++) {
            float4 v = make_float4(acc[0][r] + bb.x, acc[1][r] + bb.y,
                                   acc[2][r] + bb.z, acc[3][r] + bb.w);
            *(float4*)(xs + (ry + r) * OUTD + ox4) = v;
        }
    }
    __syncthreads();

    // --- LN2 ---
    {
        float s = 0.0f, sq = 0.0f;
        #pragma unroll
        for (int j = 0; j < 16; j++) {
            float v = xs[w * OUTD + l + 32 * j];
            s += v; sq += v * v;
        }
        #pragma unroll
        for (int o = 16; o > 0; o >>= 1) {
            s  += __shfl_xor_sync(0xFFFFFFFFu, s, o);
            sq += __shfl_xor_sync(0xFFFFFFFFu, sq, o);
        }
        const float mean = s * (1.0f / OUTD);
        const float var  = sq * (1.0f / OUTD) - mean * mean;
        const float rstd = rsqrtf(var + 1e-5f);
        #pragma unroll
        for (int j = 0; j < 16; j++) {
            const int idx = l + 32 * j;
            float v = xs[w * OUTD + idx];
            xs[w * OUTD + idx] = (v - mean) * rstd * g2[idx] + be2[idx];
        }
    }
    __syncthreads();

    // --- write theta tile ---
    {
        float4* dst = (float4*)(theta + (size_t)row0 * OUTD);
        const float4* src = (const float4*)xs;
        #pragma unroll
        for (int i = 0; i < 4; i++)
            dst[t + 512 * i] = src[t + 512 * i];
    }
}

// ---------------------------------------------------------------------------
// Launch. Output layout: [theta (B*512) | alpha (B*64) | mu (B*256)]
// ---------------------------------------------------------------------------
extern "C" void kernel_launch(void* const* d_in, const int* in_sizes, int n_in,
                              void* d_out, int out_size)
{
    const float* h       = (const float*)d_in[0];
    const float* log_tau = (const float*)d_in[1];
    const float* w1      = (const float*)d_in[2];
    const float* b1      = (const float*)d_in[3];
    const float* g1      = (const float*)d_in[4];
    const float* be1     = (const float*)d_in[5];
    const float* w2      = (const float*)d_in[6];
    const float* b2      = (const float*)d_in[7];
    const float* g2      = (const float*)d_in[8];
    const float* be2     = (const float*)d_in[9];

    const int batch = in_sizes[0] / (NN * DD);

    float* out   = (float*)d_out;
    float* theta = out;
    float* alpha = out + (size_t)batch * OUTD;
    float* mu    = out + (size_t)batch * OUTD + (size_t)batch * NN;

    float* w1t_dev = nullptr;
    float* w2t_dev = nullptr;
    cudaGetSymbolAddress((void**)&w1t_dev, g_w1t);
    cudaGetSymbolAddress((void**)&w2t_dev, g_w2t);

    dim3 tb(32, 8);
    transpose_kernel<<<dim3(DD / 32, OUTD / 32), tb>>>(w1, w1t_dev, OUTD, DD);
    transpose_kernel<<<dim3(OUTD / 32, OUTD / 32), tb>>>(w2, w2t_dev, OUTD, OUTD);

    cluster_kernel<<<batch, 256>>>(h, log_tau, alpha, mu);
    mlp_kernel<<<batch / 16, 512>>>(mu, b1, g1, be1, b2, g2, be2, theta);
}

// round 3
// speedup vs baseline: 2.5282x; 1.2567x over previous
#include <cuda_runtime.h>
#include <math.h>

#define BB   4096
#define NN   64
#define DD   256
#define OUTD 512
#define NIT  3

// Transposed weight scratch
__device__ float g_w1t[DD * OUTD];    // [256][512]
__device__ float g_w2t[OUTD * OUTD];  // [512][512]

// ---- packed f32x2 helpers (sm_100+) ----
#define FMA2(d, a, b) asm("fma.rn.f32x2 %0, %1, %2, %0;" : "+l"(d) : "l"(a), "l"(b))
#define DUP2(d, s)    asm("mov.b64 %0, {%1, %1};" : "=l"(d) : "r"(s))
#define UNPK2(lo, hi, d) asm("mov.b64 {%0, %1}, %2;" : "=r"(lo), "=r"(hi) : "l"(d))

// ---------------------------------------------------------------------------
// Tiled transpose: out[c][r] = in[r][c], in is [R][C]
// ---------------------------------------------------------------------------
__global__ void transpose_kernel(const float* __restrict__ in,
                                 float* __restrict__ out, int R, int C)
{
    __shared__ float tile[32][33];
    const int c0 = blockIdx.x * 32;
    const int r0 = blockIdx.y * 32;
    const int tx = threadIdx.x;
    const int ty = threadIdx.y;
    #pragma unroll
    for (int i = 0; i < 4; i++) {
        int r = r0 + ty + 8 * i;
        int c = c0 + tx;
        if (r < R && c < C) tile[ty + 8 * i][tx] = in[(size_t)r * C + c];
    }
    __syncthreads();
    #pragma unroll
    for (int i = 0; i < 4; i++) {
        int c = c0 + ty + 8 * i;
        int r = r0 + tx;
        if (r < R && c < C) out[(size_t)c * R + r] = tile[tx][ty + 8 * i];
    }
}

__device__ __forceinline__ float wsum(float v) {
    #pragma unroll
    for (int o = 16; o > 0; o >>= 1) v += __shfl_xor_sync(0xFFFFFFFFu, v, o);
    return v;
}

// ---------------------------------------------------------------------------
// Kernel 1: soft clustering. 512 threads/block, one batch per block.
// Warp w (0..15) owns rows 4w..4w+3; lane l owns dims [8l, 8l+8).
// mu state lives in smem; per-dim reductions are scalar & conflict-free.
// ---------------------------------------------------------------------------
__global__ void __launch_bounds__(512, 2)
cluster_kernel(const float* __restrict__ h,
               const float* __restrict__ log_tau,
               float* __restrict__ out_alpha,   // [B, 64]
               float* __restrict__ out_mu)      // [B, 256]
{
    __shared__ float pmu[16][DD];    // per-warp partial mu (16KB)
    __shared__ float mun_s[DD];
    __shared__ float simv[NN];
    __shared__ float alpha_s[NN];
    __shared__ float red[8];

    const int b = blockIdx.x;
    const int t = threadIdx.x;       // 0..511
    const int w = t >> 5;            // 0..15
    const int l = t & 31;

    const float* hb = h + (size_t)b * NN * DD;

    // --- load 4 rows x 8 dims into registers ---
    float4 hv[4][2];
    #pragma unroll
    for (int r = 0; r < 4; r++) {
        const float* p = hb + (size_t)(4 * w + r) * DD + 8 * l;
        hv[r][0] = *(const float4*)(p);
        hv[r][1] = *(const float4*)(p + 4);
    }

    float tau = expf(log_tau[0]);
    tau = fminf(fmaxf(tau, 0.01f), 2.0f);
    const float inv_tau = 1.0f / tau;

    // --- per-row inverse norms, pre-multiplied by 1/tau ---
    float rni[4];
    #pragma unroll
    for (int r = 0; r < 4; r++) {
        float4 a = hv[r][0], c = hv[r][1];
        float s = a.x*a.x + a.y*a.y + a.z*a.z + a.w*a.w
                + c.x*c.x + c.y*c.y + c.z*c.z + c.w*c.w;
        s = wsum(s);
        rni[r] = inv_tau / fmaxf(sqrtf(s), 1e-12f);
    }

    // --- per-warp partial sums for initial mean ---
    float pm[8];
    #pragma unroll
    for (int i = 0; i < 8; i++) pm[i] = 0.0f;
    #pragma unroll
    for (int r = 0; r < 4; r++) {
        pm[0] += hv[r][0].x; pm[1] += hv[r][0].y;
        pm[2] += hv[r][0].z; pm[3] += hv[r][0].w;
        pm[4] += hv[r][1].x; pm[5] += hv[r][1].y;
        pm[6] += hv[r][1].z; pm[7] += hv[r][1].w;
    }
    ((float4*)&pmu[w][8 * l])[0] = make_float4(pm[0], pm[1], pm[2], pm[3]);
    ((float4*)&pmu[w][8 * l])[1] = make_float4(pm[4], pm[5], pm[6], pm[7]);
    __syncthreads();

    // threads 0..255 own one mu dim each (scalar, conflict-free column reads)
    float mval = 0.0f;
    if (t < DD) {
        #pragma unroll
        for (int ww = 0; ww < 16; ww++) mval += pmu[ww][t];
        mval *= (1.0f / NN);
    }

    // --- 3 EM iterations ---
    for (int it = 0; it < NIT; it++) {
        // ||mu||: reduce mval^2 over dims (warps 0..7)
        if (t < DD) {
            float s = wsum(mval * mval);
            if (l == 0) red[w] = s;
        }
        __syncthreads();
        if (t < DD) {
            float tot = red[0] + red[1] + red[2] + red[3]
                      + red[4] + red[5] + red[6] + red[7];
            mun_s[t] = mval / fmaxf(sqrtf(tot), 1e-12f);
        }
        __syncthreads();

        // sim for this warp's 4 rows
        float4 mn0 = *(const float4*)(mun_s + 8 * l);
        float4 mn1 = *(const float4*)(mun_s + 8 * l + 4);
        #pragma unroll
        for (int r = 0; r < 4; r++) {
            float4 a = hv[r][0], c = hv[r][1];
            float d = a.x*mn0.x + a.y*mn0.y + a.z*mn0.z + a.w*mn0.w
                    + c.x*mn1.x + c.y*mn1.y + c.z*mn1.z + c.w*mn1.w;
            d = wsum(d);
            if (l == 0) simv[4 * w + r] = d * rni[r];
        }
        __syncthreads();

        // softmax over 64 (warp 0)
        if (w == 0) {
            float a = simv[l];
            float c = simv[l + 32];
            float mx = fmaxf(a, c);
            #pragma unroll
            for (int o = 16; o > 0; o >>= 1)
                mx = fmaxf(mx, __shfl_xor_sync(0xFFFFFFFFu, mx, o));
            float e0 = expf(a - mx);
            float e1 = expf(c - mx);
            float ss = wsum(e0 + e1);
            float inv = 1.0f / ss;
            alpha_s[l]      = e0 * inv;
            alpha_s[l + 32] = e1 * inv;
        }
        __syncthreads();

        // mu update: per-warp partials, then per-dim scalar reduce
        float al[4];
        #pragma unroll
        for (int r = 0; r < 4; r++) al[r] = alpha_s[4 * w + r];
        #pragma unroll
        for (int i = 0; i < 8; i++) pm[i] = 0.0f;
        #pragma unroll
        for (int r = 0; r < 4; r++) {
            const float a = al[r];
            pm[0] += a * hv[r][0].x; pm[1] += a * hv[r][0].y;
            pm[2] += a * hv[r][0].z; pm[3] += a * hv[r][0].w;
            pm[4] += a * hv[r][1].x; pm[5] += a * hv[r][1].y;
            pm[6] += a * hv[r][1].z; pm[7] += a * hv[r][1].w;
        }
        ((float4*)&pmu[w][8 * l])[0] = make_float4(pm[0], pm[1], pm[2], pm[3]);
        ((float4*)&pmu[w][8 * l])[1] = make_float4(pm[4], pm[5], pm[6], pm[7]);
        __syncthreads();
        if (t < DD) {
            float acc = 0.0f;
            #pragma unroll
            for (int ww = 0; ww < 16; ww++) acc += pmu[ww][t];
            mval = acc;
        }
    }

    // --- outputs ---
    if (t < NN) out_alpha[(size_t)b * NN + t] = alpha_s[t];
    if (t < DD) out_mu[(size_t)b * DD + t] = mval;
}

// ---------------------------------------------------------------------------
// Kernel 2: fused MLP with transposed weights and packed f32x2 FFMA.
// 512 threads, 16 rows/block. Thread tile: 4 consecutive cols x 4 rows.
// ---------------------------------------------------------------------------
__global__ void __launch_bounds__(512, 2)
mlp_kernel(const float* __restrict__ mu_in,   // [B, 256]
           const float* __restrict__ b1,
           const float* __restrict__ g1,
           const float* __restrict__ be1,
           const float* __restrict__ b2,
           const float* __restrict__ g2,
           const float* __restrict__ be2,
           float* __restrict__ theta)         // [B, 512]
{
    __shared__ float xs[16 * OUTD];           // 32KB

    const int t = threadIdx.x;
    const int row0 = blockIdx.x * 16;
    const int ox4 = (t & 127) * 4;
    const int ry = (t >> 7) * 4;
    const int w = t >> 5;                      // LN row
    const int l = t & 31;

    // --- load mu tile [16,256] ---
    {
        const float4* src = (const float4*)(mu_in + (size_t)row0 * DD);
        float4* dst = (float4*)xs;
        dst[t]       = src[t];
        dst[t + 512] = src[t + 512];
    }
    __syncthreads();

    unsigned long long a01[4], a23[4];
    #pragma unroll
    for (int r = 0; r < 4; r++) { a01[r] = 0ull; a23[r] = 0ull; }

    // --- GEMM1: y1 = mu @ w1^T (packed over column pairs) ---
    for (int k = 0; k < DD; k += 4) {
        float m[4][4];
        #pragma unroll
        for (int r = 0; r < 4; r++) {
            float4 mv = *(const float4*)(xs + (ry + r) * DD + k);
            m[r][0] = mv.x; m[r][1] = mv.y; m[r][2] = mv.z; m[r][3] = mv.w;
        }
        #pragma unroll
        for (int kk = 0; kk < 4; kk++) {
            ulonglong2 wp = *(const ulonglong2*)(g_w1t + (size_t)(k + kk) * OUTD + ox4);
            #pragma unroll
            for (int r = 0; r < 4; r++) {
                unsigned long long d;
                DUP2(d, __float_as_uint(m[r][kk]));
                FMA2(a01[r], wp.x, d);
                FMA2(a23[r], wp.y, d);
            }
        }
    }
    __syncthreads();

    // --- y1 + b1 into xs[16][512] ---
    {
        const float4 bb = *(const float4*)(b1 + ox4);
        #pragma unroll
        for (int r = 0; r < 4; r++) {
            unsigned u0, u1, u2, u3;
            UNPK2(u0, u1, a01[r]);
            UNPK2(u2, u3, a23[r]);
            float4 v = make_float4(__uint_as_float(u0) + bb.x,
                                   __uint_as_float(u1) + bb.y,
                                   __uint_as_float(u2) + bb.z,
                                   __uint_as_float(u3) + bb.w);
            *(float4*)(xs + (ry + r) * OUTD + ox4) = v;
        }
    }
    __syncthreads();

    // --- LN1 + exact GELU (warp w handles row w) ---
    {
        float s = 0.0f, sq = 0.0f;
        #pragma unroll
        for (int j = 0; j < 16; j++) {
            float v = xs[w * OUTD + l + 32 * j];
            s += v; sq += v * v;
        }
        #pragma unroll
        for (int o = 16; o > 0; o >>= 1) {
            s  += __shfl_xor_sync(0xFFFFFFFFu, s, o);
            sq += __shfl_xor_sync(0xFFFFFFFFu, sq, o);
        }
        const float mean = s * (1.0f / OUTD);
        const float var  = sq * (1.0f / OUTD) - mean * mean;
        const float rstd = rsqrtf(var + 1e-5f);
        #pragma unroll
        for (int j = 0; j < 16; j++) {
            const int idx = l + 32 * j;
            float v = xs[w * OUTD + idx];
            v = (v - mean) * rstd * g1[idx] + be1[idx];
            v = 0.5f * v * (1.0f + erff(v * 0.70710678118654752f));
            xs[w * OUTD + idx] = v;
        }
    }
    __syncthreads();

    // --- GEMM2: y2 = x @ w2^T ---
    #pragma unroll
    for (int r = 0; r < 4; r++) { a01[r] = 0ull; a23[r] = 0ull; }

    for (int k = 0; k < OUTD; k += 4) {
        float m[4][4];
        #pragma unroll
        for (int r = 0; r < 4; r++) {
            float4 mv = *(const float4*)(xs + (ry + r) * OUTD + k);
            m[r][0] = mv.x; m[r][1] = mv.y; m[r][2] = mv.z; m[r][3] = mv.w;
        }
        #pragma unroll
        for (int kk = 0; kk < 4; kk++) {
            ulonglong2 wp = *(const ulonglong2*)(g_w2t + (size_t)(k + kk) * OUTD + ox4);
            #pragma unroll
            for (int r = 0; r < 4; r++) {
                unsigned long long d;
                DUP2(d, __float_as_uint(m[r][kk]));
                FMA2(a01[r], wp.x, d);
                FMA2(a23[r], wp.y, d);
            }
        }
    }
    __syncthreads();

    // --- y2 + b2 ---
    {
        const float4 bb = *(const float4*)(b2 + ox4);
        #pragma unroll
        for (int r = 0; r < 4; r++) {
            unsigned u0, u1, u2, u3;
            UNPK2(u0, u1, a01[r]);
            UNPK2(u2, u3, a23[r]);
            float4 v = make_float4(__uint_as_float(u0) + bb.x,
                                   __uint_as_float(u1) + bb.y,
                                   __uint_as_float(u2) + bb.z,
                                   __uint_as_float(u3) + bb.w);
            *(float4*)(xs + (ry + r) * OUTD + ox4) = v;
        }
    }
    __syncthreads();

    // --- LN2 ---
    {
        float s = 0.0f, sq = 0.0f;
        #pragma unroll
        for (int j = 0; j < 16; j++) {
            float v = xs[w * OUTD + l + 32 * j];
            s += v; sq += v * v;
        }
        #pragma unroll
        for (int o = 16; o > 0; o >>= 1) {
            s  += __shfl_xor_sync(0xFFFFFFFFu, s, o);
            sq += __shfl_xor_sync(0xFFFFFFFFu, sq, o);
        }
        const float mean = s * (1.0f / OUTD);
        const float var  = sq * (1.0f / OUTD) - mean * mean;
        const float rstd = rsqrtf(var + 1e-5f);
        #pragma unroll
        for (int j = 0; j < 16; j++) {
            const int idx = l + 32 * j;
            float v = xs[w * OUTD + idx];
            xs[w * OUTD + idx] = (v - mean) * rstd * g2[idx] + be2[idx];
        }
    }
    __syncthreads();

    // --- write theta tile ---
    {
        float4* dst = (float4*)(theta + (size_t)row0 * OUTD);
        const float4* src = (const float4*)xs;
        #pragma unroll
        for (int i = 0; i < 4; i++)
            dst[t + 512 * i] = src[t + 512 * i];
    }
}

// ---------------------------------------------------------------------------
// Launch. Output layout: [theta (B*512) | alpha (B*64) | mu (B*256)]
// ---------------------------------------------------------------------------
extern "C" void kernel_launch(void* const* d_in, const int* in_sizes, int n_in,
                              void* d_out, int out_size)
{
    const float* h       = (const float*)d_in[0];
    const float* log_tau = (const float*)d_in[1];
    const float* w1      = (const float*)d_in[2];
    const float* b1      = (const float*)d_in[3];
    const float* g1      = (const float*)d_in[4];
    const float* be1     = (const float*)d_in[5];
    const float* w2      = (const float*)d_in[6];
    const float* b2      = (const float*)d_in[7];
    const float* g2      = (const float*)d_in[8];
    const float* be2     = (const float*)d_in[9];

    const int batch = in_sizes[0] / (NN * DD);

    float* out   = (float*)d_out;
    float* theta = out;
    float* alpha = out + (size_t)batch * OUTD;
    float* mu    = out + (size_t)batch * OUTD + (size_t)batch * NN;

    float* w1t_dev = nullptr;
    float* w2t_dev = nullptr;
    cudaGetSymbolAddress((void**)&w1t_dev, g_w1t);
    cudaGetSymbolAddress((void**)&w2t_dev, g_w2t);

    dim3 tb(32, 8);
    transpose_kernel<<<dim3(DD / 32, OUTD / 32), tb>>>(w1, w1t_dev, OUTD, DD);
    transpose_kernel<<<dim3(OUTD / 32, OUTD / 32), tb>>>(w2, w2t_dev, OUTD, OUTD);

    cluster_kernel<<<batch, 512>>>(h, log_tau, alpha, mu);
    mlp_kernel<<<batch / 16, 512>>>(mu, b1, g1, be1, b2, g2, be2, theta);
}